// round 10
// baseline (speedup 1.0000x reference)
#include <cuda_runtime.h>
#include <cuda_bf16.h>
#include <cstdint>

// x:   [B=64, C=12, 224, 224] fp32
// w:   [C=12, E=768] fp32
// out: [B=64, P=196, E=768] fp32
//
// CTA = (b, pi) strip: 12 channels x (16 rows x 224 cols) of x.
// Each channel strip is a CONTIGUOUS 14336B block -> cp.async.bulk (TMA)
// into a 2-deep smem ping-pong; the TMA engine keeps DRAM saturated
// independent of warp compute/barriers. Consumers accumulate per-channel
// partials in registers (zero shuffles in the loop), then one end-stage
// fold + tiny smem reduce -> pooled[14][12], then the C->E epilogue.

#define IMG   224
#define NP    14
#define C_IN  12
#define EMBED 768
#define NTH   448
#define STRIP_FLOATS (16 * IMG)          // 3584
#define STRIP_BYTES  (STRIP_FLOATS * 4)  // 14336

struct __align__(128) SmemLayout {
    float buf[2][STRIP_FLOATS];          // 28672 B
    float rps[112][C_IN];                // 5376 B  (row-pair sums)
    float pooled[NP][C_IN];              // 672 B
    unsigned long long mbar[2];
};

__device__ __forceinline__ uint32_t s2u(const void* p) {
    return (uint32_t)__cvta_generic_to_shared(p);
}
__device__ __forceinline__ void mbar_init(uint32_t a, uint32_t cnt) {
    asm volatile("mbarrier.init.shared.b64 [%0], %1;" :: "r"(a), "r"(cnt) : "memory");
}
__device__ __forceinline__ void mbar_expect_tx(uint32_t a, uint32_t bytes) {
    asm volatile("mbarrier.arrive.expect_tx.shared.b64 _, [%0], %1;"
                 :: "r"(a), "r"(bytes) : "memory");
}
__device__ __forceinline__ void mbar_wait(uint32_t a, uint32_t parity) {
    asm volatile(
        "{\n\t.reg .pred P;\n\t"
        "WAIT_%=:\n\t"
        "mbarrier.try_wait.parity.acquire.cta.shared::cta.b64 P, [%0], %1, 0x989680;\n\t"
        "@P bra DONE_%=;\n\t"
        "bra WAIT_%=;\n\t"
        "DONE_%=:\n\t}"
        :: "r"(a), "r"(parity) : "memory");
}
__device__ __forceinline__ void bulk_copy(uint32_t dst, const void* src,
                                          uint32_t bytes, uint32_t mbar) {
    asm volatile(
        "cp.async.bulk.shared::cta.global.mbarrier::complete_tx::bytes [%0], [%1], %2, [%3];"
        :: "r"(dst), "l"(src), "r"(bytes), "r"(mbar) : "memory");
}

__global__ __launch_bounds__(NTH, 4) void fused_tma_kernel(
    const float* __restrict__ x,
    const float* __restrict__ w,
    float* __restrict__ out)
{
    __shared__ SmemLayout s;
    const int pi = blockIdx.x;           // patch row 0..13
    const int b  = blockIdx.y;           // 0..63
    const int t  = threadIdx.x;

    const float* src_base = x + ((size_t)b * C_IN * IMG + (size_t)pi * 16) * IMG;

    const uint32_t mb0 = s2u(&s.mbar[0]);
    const uint32_t mb1 = s2u(&s.mbar[1]);
    if (t == 0) { mbar_init(mb0, 1); mbar_init(mb1, 1); }
    __syncthreads();
    if (t == 0) {
        mbar_expect_tx(mb0, STRIP_BYTES);
        bulk_copy(s2u(&s.buf[0][0]), src_base,                           STRIP_BYTES, mb0);
        mbar_expect_tx(mb1, STRIP_BYTES);
        bulk_copy(s2u(&s.buf[1][0]), src_base + (size_t)IMG * IMG,       STRIP_BYTES, mb1);
    }

    // ---- channel loop: thread t owns float4 slots t and t+448 (same patch:
    //      slot s -> row s/56, q = s%56, patch q/4; t+448 = same q, row+8) ----
    float partial[C_IN];
    #pragma unroll
    for (int c = 0; c < C_IN; ++c) {
        const uint32_t mb = (c & 1) ? mb1 : mb0;
        mbar_wait(mb, (c >> 1) & 1);

        const float4 v1 = *reinterpret_cast<const float4*>(&s.buf[c & 1][t * 4]);
        const float4 v2 = *reinterpret_cast<const float4*>(&s.buf[c & 1][(t + NTH) * 4]);
        partial[c] = ((v1.x + v1.y) + (v1.z + v1.w)) + ((v2.x + v2.y) + (v2.z + v2.w));

        __syncthreads();   // all reads of buf[c&1] done -> safe to overwrite
        if (t == 0 && c + 2 < C_IN) {
            mbar_expect_tx(mb, STRIP_BYTES);
            bulk_copy(s2u(&s.buf[c & 1][0]),
                      src_base + (size_t)(c + 2) * IMG * IMG, STRIP_BYTES, mb);
        }
    }

    // ---- end-stage fold: threads 4k..4k+3 share one (row, patch) quad ----
    #pragma unroll
    for (int c = 0; c < C_IN; ++c) {
        float v = partial[c];
        v += __shfl_xor_sync(0xffffffffu, v, 1);
        v += __shfl_xor_sync(0xffffffffu, v, 2);
        partial[c] = v;
    }
    if ((t & 3) == 0) {
        const int idx = t >> 2;          // = r*14 + p  (r = row-pair 0..7)
        #pragma unroll
        for (int c = 0; c < C_IN; ++c) s.rps[idx][c] = partial[c];
    }
    __syncthreads();

    if (t < NP * C_IN) {                 // 168 reducers
        const int p = t / C_IN, c = t % C_IN;
        float acc = 0.f;
        #pragma unroll
        for (int r = 0; r < 8; ++r) acc += s.rps[r * NP + p][c];
        s.pooled[p][c] = acc;
    }
    __syncthreads();

    // ---- phase 2: 384 threads, each (e4, half) emits 7 patches ----
    if (t < 384) {
        const int e4   = t % 192;
        const int half = t / 192;
        float4 acc[7];
        #pragma unroll
        for (int j = 0; j < 7; ++j) acc[j] = make_float4(0.f, 0.f, 0.f, 0.f);

        #pragma unroll
        for (int c = 0; c < C_IN; ++c) {
            const float4 wv = *reinterpret_cast<const float4*>(&w[c * EMBED + e4 * 4]);
            #pragma unroll
            for (int j = 0; j < 7; ++j) {
                const float pc = s.pooled[half * 7 + j][c];
                acc[j].x = fmaf(pc, wv.x, acc[j].x);
                acc[j].y = fmaf(pc, wv.y, acc[j].y);
                acc[j].z = fmaf(pc, wv.z, acc[j].z);
                acc[j].w = fmaf(pc, wv.w, acc[j].w);
            }
        }

        float* o = out + (((size_t)b * (NP * NP)) + (size_t)pi * NP + half * 7) * EMBED
                       + e4 * 4;
        #pragma unroll
        for (int j = 0; j < 7; ++j)
            *reinterpret_cast<float4*>(o + (size_t)j * EMBED) = acc[j];
    }
}

extern "C" void kernel_launch(void* const* d_in, const int* in_sizes, int n_in,
                              void* d_out, int out_size)
{
    const float* x = (const float*)d_in[0];
    const float* w = (const float*)d_in[1];
    float* out = (float*)d_out;

    dim3 grid(NP, 64);   // 896 CTAs
    fused_tma_kernel<<<grid, NTH>>>(x, w, out);
}

// round 11
// speedup vs baseline: 1.9940x; 1.9940x over previous
#include <cuda_runtime.h>
#include <cuda_bf16.h>
#include <cstdint>

// x:   [B=64, C=12, 224, 224] fp32
// w:   [C=12, E=768] fp32
// out: [B=64, P=196, E=768] fp32
//
// CTA = 2x2 patch block (32x32 pixels x 12 channels = 48 KB of x).
// Phase 1: warp = channel; each thread fires 8 independent cp.async.cg
//          (16B GMEM->smem, no register staging, L1-bypass), waits once,
//          reads back 8 conflict-free float4 from smem, dual shuffle-reduce.
// Phase 2: each thread loads w[:, e4] once and emits TWO patch outputs.

#define IMG    224
#define NP     14
#define C_IN   12
#define EMBED  768
#define NTH    384

struct SmemT {
    union {
        float4 buf[C_IN * 8 * 32];   // 48 KB: [channel][k][lane]
        float  pooled[C_IN][4];      // aliases buf after consumption barrier
    };
};

__device__ __forceinline__ void cp16(uint32_t dst, const float* src) {
    asm volatile("cp.async.cg.shared.global [%0], [%1], 16;"
                 :: "r"(dst), "l"(src) : "memory");
}

__global__ __launch_bounds__(NTH, 4) void patch_block_cpasync_kernel(
    const float* __restrict__ x,
    const float* __restrict__ w,
    float* __restrict__ out)
{
    __shared__ SmemT s;

    const int pp  = blockIdx.x;        // patch-col pair 0..6
    const int pr  = blockIdx.y;        // patch-row pair 0..6
    const int b   = blockIdx.z;        // 0..63
    const int t   = threadIdx.x;
    const int warp = t >> 5;           // channel 0..11
    const int lane = t & 31;
    const int q8  = lane & 7;          // float4 col within the 32-float row
    const int rh  = lane >> 3;         // row phase 0..3

    // ---- Phase 1a: fire 8 independent cp.async (rows rh + 4k) ----
    const float* base = x
        + (((size_t)(b * C_IN + warp)) * IMG + (size_t)pr * 32 + rh) * IMG
        + (size_t)pp * 32 + q8 * 4;

    const uint32_t dst0 = (uint32_t)__cvta_generic_to_shared(
        &s.buf[(warp * 8) * 32 + lane]);

    #pragma unroll
    for (int k = 0; k < 8; ++k)
        cp16(dst0 + k * 32 * 16, base + (size_t)(4 * k) * IMG);

    asm volatile("cp.async.commit_group;" ::: "memory");
    asm volatile("cp.async.wait_group 0;" ::: "memory");
    __syncthreads();

    // ---- Phase 1b: read back own slots (conflict-free) and reduce ----
    const float4 u0 = s.buf[(warp * 8 + 0) * 32 + lane];
    const float4 u1 = s.buf[(warp * 8 + 1) * 32 + lane];
    const float4 u2 = s.buf[(warp * 8 + 2) * 32 + lane];
    const float4 u3 = s.buf[(warp * 8 + 3) * 32 + lane];
    const float4 d0 = s.buf[(warp * 8 + 4) * 32 + lane];
    const float4 d1 = s.buf[(warp * 8 + 5) * 32 + lane];
    const float4 d2 = s.buf[(warp * 8 + 6) * 32 + lane];
    const float4 d3 = s.buf[(warp * 8 + 7) * 32 + lane];

    float st = (((u0.x + u0.y) + (u0.z + u0.w)) + ((u1.x + u1.y) + (u1.z + u1.w)))
             + (((u2.x + u2.y) + (u2.z + u2.w)) + ((u3.x + u3.y) + (u3.z + u3.w)));
    float sb = (((d0.x + d0.y) + (d0.z + d0.w)) + ((d1.x + d1.y) + (d1.z + d1.w)))
             + (((d2.x + d2.y) + (d2.z + d2.w)) + ((d3.x + d3.y) + (d3.z + d3.w)));

    // Fold lane bits 0,1 (float4 cols within a patch) and 3,4 (row phases);
    // bit 2 (q8>>2) = patch column survives.
    st += __shfl_xor_sync(0xffffffffu, st, 1);
    sb += __shfl_xor_sync(0xffffffffu, sb, 1);
    st += __shfl_xor_sync(0xffffffffu, st, 2);
    sb += __shfl_xor_sync(0xffffffffu, sb, 2);
    st += __shfl_xor_sync(0xffffffffu, st, 8);
    sb += __shfl_xor_sync(0xffffffffu, sb, 8);
    st += __shfl_xor_sync(0xffffffffu, st, 16);
    sb += __shfl_xor_sync(0xffffffffu, sb, 16);

    // All smem reads of buf are complete in every warp before we alias it.
    __syncthreads();

    if ((lane & 27) == 0) {            // lanes 0 and 4
        const int pc = (lane >> 2) & 1;
        s.pooled[warp][pc]     = st;   // top patch row
        s.pooled[warp][2 + pc] = sb;   // bottom patch row
    }
    __syncthreads();

    // ---- Phase 2: one w column read serves two patch outputs ----
    const int e4 = t % 192;            // output float4 slot
    const int lr = t / 192;            // local patch row 0/1 (uniform per warp)

    float4 acc0 = make_float4(0.f, 0.f, 0.f, 0.f);  // patch col 0
    float4 acc1 = make_float4(0.f, 0.f, 0.f, 0.f);  // patch col 1
    #pragma unroll
    for (int c = 0; c < C_IN; ++c) {
        const float4 wv = *reinterpret_cast<const float4*>(&w[c * EMBED + e4 * 4]);
        const float p0 = s.pooled[c][lr * 2 + 0];
        const float p1 = s.pooled[c][lr * 2 + 1];
        acc0.x = fmaf(p0, wv.x, acc0.x);  acc1.x = fmaf(p1, wv.x, acc1.x);
        acc0.y = fmaf(p0, wv.y, acc0.y);  acc1.y = fmaf(p1, wv.y, acc1.y);
        acc0.z = fmaf(p0, wv.z, acc0.z);  acc1.z = fmaf(p1, wv.z, acc1.z);
        acc0.w = fmaf(p0, wv.w, acc0.w);  acc1.w = fmaf(p1, wv.w, acc1.w);
    }

    const int pi = pr * 2 + lr;        // global patch row
    const int pj = pp * 2;             // global patch col (even)
    float* o = out + ((size_t)b * (NP * NP) + (size_t)pi * NP + pj) * EMBED + e4 * 4;
    *reinterpret_cast<float4*>(o)         = acc0;   // patch (pi, pj)
    *reinterpret_cast<float4*>(o + EMBED) = acc1;   // patch (pi, pj+1)
}

extern "C" void kernel_launch(void* const* d_in, const int* in_sizes, int n_in,
                              void* d_out, int out_size)
{
    const float* x = (const float*)d_in[0];
    const float* w = (const float*)d_in[1];
    float* out = (float*)d_out;

    dim3 grid(7, 7, 64);   // 3136 CTAs
    patch_block_cpasync_kernel<<<grid, NTH>>>(x, w, out);
}